// round 3
// baseline (speedup 1.0000x reference)
#include <cuda_runtime.h>

typedef unsigned long long ull;

#define ROWS_PER_CTA 32
#define RPW 4
#define NTHREADS 256
#define GRID 1024   /* 32768 rows / 32 */

// shared layout (bytes)
#define OFF_XD   98304                    // after 2x48KB Wc double buffer
#define OFF_U    (OFF_XD + 64*34*8)       // 115712
#define OFF_V    (OFF_U + 3072*4)         // 128000
#define OFF_ADJJ (OFF_V + 192)            // 128192
#define OFF_RS   (OFF_ADJJ + 96)          // 128288
#define SMEM_BYTES (OFF_RS + 768 + 32)    // 129088

// ---------------- device-global precomputed tables ----------------
__device__ float g_Wc[64 * 1536];   // [f][n][k]  = sum_h Wp[f, n*64+h] * W[h,k]
__device__ float g_u[64 * 48];      // [f][n], [f][24+n]
__device__ float g_v[48];
__device__ float g_bc[24 * 64];     // bc[n,k]

// ---------------- helpers ----------------
__device__ __forceinline__ ull packdup(float v) {
    ull r; asm("mov.b64 %0, {%1, %1};" : "=l"(r) : "f"(v)); return r;
}
#define FMA2(d, a_, b_, c_) \
    asm("fma.rn.f32x2 %0, %1, %2, %3;" : "=l"(d) : "l"(a_), "l"(b_), "l"(c_))
#define ADD2(d, a_, b_) \
    asm("add.rn.f32x2 %0, %1, %2;" : "=l"(d) : "l"(a_), "l"(b_))

__device__ __forceinline__ void cp16(unsigned smaddr, const void* g) {
    asm volatile("cp.async.cg.shared.global [%0], [%1], 16;" :: "r"(smaddr), "l"(g));
}

// ---------------- prep kernel 1: Wc and u ----------------
__global__ void prep_wc(const float* __restrict__ Wp, const float* __restrict__ W,
                        const float* __restrict__ a) {
    int b = blockIdx.x;           // 0..1535
    int n = b >> 6;               // 0..23
    int f = b & 63;               // 0..63
    int k = threadIdx.x;          // 0..63
    float acc = 0.f;
#pragma unroll 8
    for (int h = 0; h < 64; h++)
        acc = fmaf(Wp[f * 1536 + n * 64 + h], W[h * 64 + k], acc);
    g_Wc[f * 1536 + n * 64 + k] = acc;

    float p1 = acc * a[k];
    float p2 = acc * a[64 + k];
#pragma unroll
    for (int d = 16; d; d >>= 1) {
        p1 += __shfl_xor_sync(0xffffffffu, p1, d);
        p2 += __shfl_xor_sync(0xffffffffu, p2, d);
    }
    __shared__ float r1[2], r2[2];
    if ((k & 31) == 0) { r1[k >> 5] = p1; r2[k >> 5] = p2; }
    __syncthreads();
    if (k == 0) {
        g_u[f * 48 + n]      = r1[0] + r1[1];
        g_u[f * 48 + 24 + n] = r2[0] + r2[1];
    }
}

// ---------------- prep kernel 2: bc and v ----------------
__global__ void prep_bc(const float* __restrict__ bp, const float* __restrict__ W,
                        const float* __restrict__ a) {
    int n = blockIdx.x;           // 0..23
    int k = threadIdx.x;          // 0..63
    float acc = 0.f;
#pragma unroll 8
    for (int h = 0; h < 64; h++)
        acc = fmaf(bp[n * 64 + h], W[h * 64 + k], acc);
    g_bc[n * 64 + k] = acc;

    float p1 = acc * a[k];
    float p2 = acc * a[64 + k];
#pragma unroll
    for (int d = 16; d; d >>= 1) {
        p1 += __shfl_xor_sync(0xffffffffu, p1, d);
        p2 += __shfl_xor_sync(0xffffffffu, p2, d);
    }
    __shared__ float r1[2], r2[2];
    if ((k & 31) == 0) { r1[k >> 5] = p1; r2[k >> 5] = p2; }
    __syncthreads();
    if (k == 0) { g_v[n] = r1[0] + r1[1]; g_v[24 + n] = r2[0] + r2[1]; }
}

// ---------------- main fused kernel ----------------
__global__ __launch_bounds__(NTHREADS, 1)
void gat_main(const float* __restrict__ x, const int* __restrict__ adj,
              float* __restrict__ out) {
    extern __shared__ char smem[];
    float* s_wc   = (float*)smem;
    ull*   s_P    = (ull*)smem;                 // overlays Wc region in phase 2
    ull*   s_xd   = (ull*)(smem + OFF_XD);      // 64 x 34 ull, {x,x} pairs [f][row]
    float* s_u    = (float*)(smem + OFF_U);
    float* s_v    = (float*)(smem + OFF_V);
    unsigned* s_adjJ = (unsigned*)(smem + OFF_ADJJ);
    float* s_rs   = (float*)(smem + OFF_RS);    // 8 warps x 24

    const int tid  = threadIdx.x;
    const int lane = tid & 31;
    const int w    = tid >> 5;
    const int rowbase = blockIdx.x * ROWS_PER_CTA;

    const unsigned swc0 = (unsigned)__cvta_generic_to_shared(s_wc);

    // prologue: stage f-block 0 of Wc (48 KB) into buffer 0
    {
        const float* src = g_Wc;
        for (int c = tid; c < 3072; c += NTHREADS) cp16(swc0 + c * 16, src + c * 4);
        asm volatile("cp.async.commit_group;");
    }

    // stage x as duplicated {x,x} pairs: s_xd[f*34 + r]
    for (int i = tid; i < ROWS_PER_CTA * 64; i += NTHREADS) {
        int r = i >> 6, f = i & 63;
        s_xd[f * 34 + r] = packdup(x[(rowbase + r) * 64 + f]);
    }
    for (int i = tid; i < 3072; i += NTHREADS) s_u[i] = g_u[i];
    if (tid < 48) s_v[tid] = g_v[tid];
    if (tid < 24) {
        unsigned b = 0;
        for (int i = 0; i < 24; i++) b |= (adj[i * 24 + tid] > 0 ? 1u : 0u) << i;
        s_adjJ[tid] = b;
    }

    // Wh accumulators: lane owns k = 2*lane, 2*lane+1, for 4 rows x 24 nodes
    ull wh[RPW][24];
#pragma unroll
    for (int n = 0; n < 24; n++) {
        ull b = ((const ull*)g_bc)[n * 32 + lane];
        wh[0][n] = b; wh[1][n] = b; wh[2][n] = b; wh[3][n] = b;
    }

    __syncthreads();

    // ---------------- phase 1: Wh = x @ Wc + bc (software-pipelined) ----------------
    for (int fb = 0; fb < 8; fb++) {
        if (fb < 7) {
            unsigned dst = swc0 + (unsigned)(((fb + 1) & 1) * 49152);
            const float* src = g_Wc + (fb + 1) * 12288;
            for (int c = tid; c < 3072; c += NTHREADS) cp16(dst + c * 16, src + c * 4);
            asm volatile("cp.async.commit_group;");
            asm volatile("cp.async.wait_group 1;");
        } else {
            asm volatile("cp.async.wait_group 0;");
        }
        __syncthreads();

        const ull* wbase = ((const ull*)(s_wc + (fb & 1) * 12288)) + lane;

        ull w2[2][4];       // double-buffered weight chunk (4 n)
        ull xs[2][4];       // double-buffered x pairs, indexed by ff&1
        {
            // preload chunk 0 (ff=0, g=0) and x for ff=0
#pragma unroll
            for (int q = 0; q < 4; q++) w2[0][q] = wbase[q * 32];
            const ulonglong2* xp = (const ulonglong2*)(s_xd + (fb * 8) * 34 + 4 * w);
            ulonglong2 xa = xp[0], xb = xp[1];
            xs[0][0] = xa.x; xs[0][1] = xa.y; xs[0][2] = xb.x; xs[0][3] = xb.y;
        }

#pragma unroll
        for (int c = 0; c < 48; c++) {          // chunk c: ff = c/6, n-group g = c%6
            const int cur = c & 1, nxt = cur ^ 1;
            const int ff = c / 6, g = c % 6;
            const int fp = ff & 1;
            if (c < 47) {                       // prefetch chunk c+1
                const int c1 = c + 1, ff1 = c1 / 6, g1 = c1 % 6;
                const ull* wr = wbase + ff1 * 768 + g1 * 128;
#pragma unroll
                for (int q = 0; q < 4; q++) w2[nxt][q] = wr[q * 32];
                if (g1 == 0) {                  // crossing into next f row
                    const ulonglong2* xp =
                        (const ulonglong2*)(s_xd + (fb * 8 + ff1) * 34 + 4 * w);
                    ulonglong2 xa = xp[0], xb = xp[1];
                    const int fp1 = ff1 & 1;
                    xs[fp1][0] = xa.x; xs[fp1][1] = xa.y;
                    xs[fp1][2] = xb.x; xs[fp1][3] = xb.y;
                }
            }
#pragma unroll
            for (int q = 0; q < 4; q++) {
                const int n = g * 4 + q;
                FMA2(wh[0][n], w2[cur][q], xs[fp][0], wh[0][n]);
                FMA2(wh[1][n], w2[cur][q], xs[fp][1], wh[1][n]);
                FMA2(wh[2][n], w2[cur][q], xs[fp][2], wh[2][n]);
                FMA2(wh[3][n], w2[cur][q], xs[fp][3], wh[3][n]);
            }
            asm volatile("" ::: "memory");      // bound prefetch distance to 1 chunk
        }
        __syncthreads();
    }

    // ---------------- phase 2: attention + aggregate ----------------
    const int ln = (lane < 24) ? lane : 0;

    // f1/f2 for all 4 samples, lane = node n
    float f1[RPW], f2[RPW];
#pragma unroll
    for (int r = 0; r < RPW; r++) { f1[r] = s_v[ln]; f2[r] = s_v[24 + ln]; }
#pragma unroll 4
    for (int f = 0; f < 64; f++) {
        float u1 = s_u[f * 48 + ln];
        float u2 = s_u[f * 48 + 24 + ln];
        const float* xr = (const float*)(s_xd + f * 34 + 4 * w);
#pragma unroll
        for (int r = 0; r < RPW; r++) {
            float xf = xr[2 * r];                      // low half of {x,x}
            f1[r] = fmaf(xf, u1, f1[r]);
            f2[r] = fmaf(xf, u2, f2[r]);
        }
    }

    ull* Pw = s_P + w * 600;        // per-warp 24 x 25 ull scratch (4.8 KB)
    const float inv24 = 1.0f / 24.0f;

#pragma unroll
    for (int r = 0; r < RPW; r++) {
        // ---- stage A: unnormalized probs, lanes = i, loop j ----
        float sse = 0.f;
        const float f1v = f1[r], f2v = f2[r];
#pragma unroll 6
        for (int j = 0; j < 24; j++) {
            float f2j = __shfl_sync(0xffffffffu, f2v, j);
            float e = f1v + f2j;
            e = (e > 0.f) ? e : 0.2f * e;              // LeakyReLU
            unsigned bits = s_adjJ[j];                 // uniform
            float p = ((bits >> lane) & 1u) ? __expf(e) : 0.f;
            sse += p;
            if (lane < 24) Pw[lane * 25 + j] = packdup(p);
        }
        // rare: fully-masked row -> reference softmax is uniform
        bool bad = (lane < 24) && (sse == 0.f);
        if (__any_sync(0xffffffffu, bad)) {
            if (bad) {
                for (int j = 0; j < 24; j++) Pw[lane * 25 + j] = packdup(1.f);
                sse = 24.f;
            }
        }
        if (lane < 24) s_rs[w * 24 + lane] = __fdividef(1.f, sse);
        __syncwarp();

        // ---- stage B: h' = attn @ Wh, lanes = k-pair, pipelined over i ----
        float acc0 = 0.f, acc1 = 0.f;
        ull pv[2][4];
        {
#pragma unroll
            for (int q = 0; q < 4; q++) pv[0][q] = Pw[q];   // i=0, g=0
        }
        ull hp0 = 0ULL, hp1 = 0ULL, hp2 = 0ULL;
        for (int i = 0; i < 24; i++) {
#pragma unroll
            for (int g = 0; g < 6; g++) {
                const int cur = g & 1, nxt = cur ^ 1;      // 6 chunks/i (even) -> parity = g&1
                // prefetch next chunk (possibly first chunk of i+1)
                if (g < 5) {
                    const ull* pr = Pw + i * 25 + (g + 1) * 4;
#pragma unroll
                    for (int q = 0; q < 4; q++) pv[nxt][q] = pr[q];
                } else if (i < 23) {
                    const ull* pr = Pw + (i + 1) * 25;
#pragma unroll
                    for (int q = 0; q < 4; q++) pv[nxt][q] = pr[q];
                }
#pragma unroll
                for (int q = 0; q < 4; q++) {
                    const int n = g * 4 + q;
                    if (g < 2)      { FMA2(hp0, pv[cur][q], wh[r][n], hp0); }
                    else if (g < 4) { FMA2(hp1, pv[cur][q], wh[r][n], hp1); }
                    else            { FMA2(hp2, pv[cur][q], wh[r][n], hp2); }
                }
                asm volatile("" ::: "memory");
            }
            ull hps, hp;
            ADD2(hps, hp0, hp1);
            ADD2(hp, hps, hp2);
            float rsv = s_rs[w * 24 + i];              // uniform
            float hx = __uint_as_float((unsigned)hp) * rsv;
            float hy = __uint_as_float((unsigned)(hp >> 32)) * rsv;
            acc0 += (hx > 0.f) ? hx : __expf(hx) - 1.f;   // ELU
            acc1 += (hy > 0.f) ? hy : __expf(hy) - 1.f;
            hp0 = hp1 = hp2 = 0ULL;
        }

        const int row = rowbase + 4 * w + r;
        float2 o; o.x = acc0 * inv24; o.y = acc1 * inv24;
        ((float2*)out)[row * 32 + lane] = o;
        __syncwarp();   // protect Pw before next sample overwrites
    }
}

// ---------------- launch ----------------
extern "C" void kernel_launch(void* const* d_in, const int* in_sizes, int n_in,
                              void* d_out, int out_size) {
    (void)in_sizes; (void)n_in; (void)out_size;
    const float* x   = (const float*)d_in[0];
    const int*   adj = (const int*)d_in[1];
    const float* Wp  = (const float*)d_in[2];
    const float* bp  = (const float*)d_in[3];
    const float* W   = (const float*)d_in[4];
    const float* a   = (const float*)d_in[5];
    float* out = (float*)d_out;

    cudaFuncSetAttribute(gat_main, cudaFuncAttributeMaxDynamicSharedMemorySize,
                         SMEM_BYTES);

    prep_wc<<<1536, 64>>>(Wp, W, a);
    prep_bc<<<24, 64>>>(bp, W, a);
    gat_main<<<GRID, NTHREADS, SMEM_BYTES>>>(x, adj, out);
}

// round 4
// speedup vs baseline: 1.0047x; 1.0047x over previous
#include <cuda_runtime.h>

typedef unsigned long long ull;

#define ROWS_PER_CTA 32
#define RPW 4
#define NTHREADS 256
#define GRID 1024   /* 32768 rows / 32 */

// shared layout (bytes)
#define OFF_XD   98304                    // after 2x48KB Wc double buffer
#define OFF_U    (OFF_XD + 64*34*8)       // 115712
#define OFF_V    (OFF_U + 3072*4)         // 128000
#define OFF_ADJJ (OFF_V + 192)            // 128192
#define OFF_RS   (OFF_ADJJ + 96)          // 128288
#define SMEM_BYTES (OFF_RS + 768 + 32)    // 129088

// ---------------- device-global precomputed tables ----------------
__device__ float g_Wc[64 * 1536];   // [f][n][k]  = sum_h Wp[f, n*64+h] * W[h,k]
__device__ float g_u[64 * 48];      // [f][n], [f][24+n]
__device__ float g_v[48];
__device__ float g_bc[24 * 64];     // bc[n,k]

// ---------------- helpers ----------------
__device__ __forceinline__ ull packdup(float v) {
    ull r; asm("mov.b64 %0, {%1, %1};" : "=l"(r) : "f"(v)); return r;
}
#define FMA2(d, a_, b_, c_) \
    asm("fma.rn.f32x2 %0, %1, %2, %3;" : "=l"(d) : "l"(a_), "l"(b_), "l"(c_))
#define ADD2(d, a_, b_) \
    asm("add.rn.f32x2 %0, %1, %2;" : "=l"(d) : "l"(a_), "l"(b_))

__device__ __forceinline__ void cp16(unsigned smaddr, const void* g) {
    asm volatile("cp.async.cg.shared.global [%0], [%1], 16;" :: "r"(smaddr), "l"(g));
}

// ---------------- prep kernel 1: Wc and u ----------------
__global__ void prep_wc(const float* __restrict__ Wp, const float* __restrict__ W,
                        const float* __restrict__ a) {
    int b = blockIdx.x;           // 0..1535
    int n = b >> 6;               // 0..23
    int f = b & 63;               // 0..63
    int k = threadIdx.x;          // 0..63
    float acc = 0.f;
#pragma unroll 8
    for (int h = 0; h < 64; h++)
        acc = fmaf(Wp[f * 1536 + n * 64 + h], W[h * 64 + k], acc);
    g_Wc[f * 1536 + n * 64 + k] = acc;

    float p1 = acc * a[k];
    float p2 = acc * a[64 + k];
#pragma unroll
    for (int d = 16; d; d >>= 1) {
        p1 += __shfl_xor_sync(0xffffffffu, p1, d);
        p2 += __shfl_xor_sync(0xffffffffu, p2, d);
    }
    __shared__ float r1[2], r2[2];
    if ((k & 31) == 0) { r1[k >> 5] = p1; r2[k >> 5] = p2; }
    __syncthreads();
    if (k == 0) {
        g_u[f * 48 + n]      = r1[0] + r1[1];
        g_u[f * 48 + 24 + n] = r2[0] + r2[1];
    }
}

// ---------------- prep kernel 2: bc and v ----------------
__global__ void prep_bc(const float* __restrict__ bp, const float* __restrict__ W,
                        const float* __restrict__ a) {
    int n = blockIdx.x;           // 0..23
    int k = threadIdx.x;          // 0..63
    float acc = 0.f;
#pragma unroll 8
    for (int h = 0; h < 64; h++)
        acc = fmaf(bp[n * 64 + h], W[h * 64 + k], acc);
    g_bc[n * 64 + k] = acc;

    float p1 = acc * a[k];
    float p2 = acc * a[64 + k];
#pragma unroll
    for (int d = 16; d; d >>= 1) {
        p1 += __shfl_xor_sync(0xffffffffu, p1, d);
        p2 += __shfl_xor_sync(0xffffffffu, p2, d);
    }
    __shared__ float r1[2], r2[2];
    if ((k & 31) == 0) { r1[k >> 5] = p1; r2[k >> 5] = p2; }
    __syncthreads();
    if (k == 0) { g_v[n] = r1[0] + r1[1]; g_v[24 + n] = r2[0] + r2[1]; }
}

// ---------------- main fused kernel ----------------
__global__ __launch_bounds__(NTHREADS, 1)
void gat_main(const float* __restrict__ x, const int* __restrict__ adj,
              float* __restrict__ out) {
    extern __shared__ char smem[];
    float* s_wc   = (float*)smem;
    ull*   s_P    = (ull*)smem;                 // overlays Wc region in phase 2
    ull*   s_xd   = (ull*)(smem + OFF_XD);      // 64 x 34 ull, {x,x} pairs [f][row]
    float* s_u    = (float*)(smem + OFF_U);
    float* s_v    = (float*)(smem + OFF_V);
    unsigned* s_adjJ = (unsigned*)(smem + OFF_ADJJ);
    float* s_rs   = (float*)(smem + OFF_RS);    // 8 warps x 24

    const int tid  = threadIdx.x;
    const int lane = tid & 31;
    const int w    = tid >> 5;
    const int rowbase = blockIdx.x * ROWS_PER_CTA;

    const unsigned swc0 = (unsigned)__cvta_generic_to_shared(s_wc);

    // prologue: stage f-block 0 of Wc (48 KB) into buffer 0
    {
        const float* src = g_Wc;
        for (int c = tid; c < 3072; c += NTHREADS) cp16(swc0 + c * 16, src + c * 4);
        asm volatile("cp.async.commit_group;");
    }

    // stage x as duplicated {x,x} pairs: s_xd[f*34 + r]
    for (int i = tid; i < ROWS_PER_CTA * 64; i += NTHREADS) {
        int r = i >> 6, f = i & 63;
        s_xd[f * 34 + r] = packdup(x[(rowbase + r) * 64 + f]);
    }
    for (int i = tid; i < 3072; i += NTHREADS) s_u[i] = g_u[i];
    if (tid < 48) s_v[tid] = g_v[tid];
    if (tid < 24) {
        unsigned b = 0;
        for (int i = 0; i < 24; i++) b |= (adj[i * 24 + tid] > 0 ? 1u : 0u) << i;
        s_adjJ[tid] = b;
    }

    // Wh accumulators: lane owns k = 2*lane, 2*lane+1, for 4 rows x 24 nodes
    ull wh[RPW][24];
#pragma unroll
    for (int n = 0; n < 24; n++) {
        ull b = ((const ull*)g_bc)[n * 32 + lane];
        wh[0][n] = b; wh[1][n] = b; wh[2][n] = b; wh[3][n] = b;
    }

    __syncthreads();

    // ---------------- phase 1: Wh = x @ Wc + bc (software-pipelined) ----------------
    for (int fb = 0; fb < 8; fb++) {
        if (fb < 7) {
            unsigned dst = swc0 + (unsigned)(((fb + 1) & 1) * 49152);
            const float* src = g_Wc + (fb + 1) * 12288;
            for (int c = tid; c < 3072; c += NTHREADS) cp16(dst + c * 16, src + c * 4);
            asm volatile("cp.async.commit_group;");
            asm volatile("cp.async.wait_group 1;");
        } else {
            asm volatile("cp.async.wait_group 0;");
        }
        __syncthreads();

        const ull* wbase = ((const ull*)(s_wc + (fb & 1) * 12288)) + lane;

        ull w2[2][4];       // double-buffered weight chunk (4 n)
        ull xs[2][4];       // double-buffered x pairs, indexed by ff&1
        {
            // preload chunk 0 (ff=0, g=0) and x for ff=0
#pragma unroll
            for (int q = 0; q < 4; q++) w2[0][q] = wbase[q * 32];
            const ulonglong2* xp = (const ulonglong2*)(s_xd + (fb * 8) * 34 + 4 * w);
            ulonglong2 xa = xp[0], xb = xp[1];
            xs[0][0] = xa.x; xs[0][1] = xa.y; xs[0][2] = xb.x; xs[0][3] = xb.y;
        }

#pragma unroll
        for (int c = 0; c < 48; c++) {          // chunk c: ff = c/6, n-group g = c%6
            const int cur = c & 1, nxt = cur ^ 1;
            const int ff = c / 6, g = c % 6;
            const int fp = ff & 1;
            if (c < 47) {                       // prefetch chunk c+1
                const int c1 = c + 1, ff1 = c1 / 6, g1 = c1 % 6;
                const ull* wr = wbase + ff1 * 768 + g1 * 128;
#pragma unroll
                for (int q = 0; q < 4; q++) w2[nxt][q] = wr[q * 32];
                if (g1 == 0) {                  // crossing into next f row
                    const ulonglong2* xp =
                        (const ulonglong2*)(s_xd + (fb * 8 + ff1) * 34 + 4 * w);
                    ulonglong2 xa = xp[0], xb = xp[1];
                    const int fp1 = ff1 & 1;
                    xs[fp1][0] = xa.x; xs[fp1][1] = xa.y;
                    xs[fp1][2] = xb.x; xs[fp1][3] = xb.y;
                }
            }
#pragma unroll
            for (int q = 0; q < 4; q++) {
                const int n = g * 4 + q;
                FMA2(wh[0][n], w2[cur][q], xs[fp][0], wh[0][n]);
                FMA2(wh[1][n], w2[cur][q], xs[fp][1], wh[1][n]);
                FMA2(wh[2][n], w2[cur][q], xs[fp][2], wh[2][n]);
                FMA2(wh[3][n], w2[cur][q], xs[fp][3], wh[3][n]);
            }
            asm volatile("" ::: "memory");      // bound prefetch distance to 1 chunk
        }
        __syncthreads();
    }

    // ---------------- phase 2: attention + aggregate ----------------
    const int ln = (lane < 24) ? lane : 0;

    // f1/f2 for all 4 samples, lane = node n
    float f1[RPW], f2[RPW];
#pragma unroll
    for (int r = 0; r < RPW; r++) { f1[r] = s_v[ln]; f2[r] = s_v[24 + ln]; }
#pragma unroll 4
    for (int f = 0; f < 64; f++) {
        float u1 = s_u[f * 48 + ln];
        float u2 = s_u[f * 48 + 24 + ln];
        const float* xr = (const float*)(s_xd + f * 34 + 4 * w);
#pragma unroll
        for (int r = 0; r < RPW; r++) {
            float xf = xr[2 * r];                      // low half of {x,x}
            f1[r] = fmaf(xf, u1, f1[r]);
            f2[r] = fmaf(xf, u2, f2[r]);
        }
    }

    ull* Pw = s_P + w * 600;        // per-warp 24 x 25 ull scratch (4.8 KB)
    const float inv24 = 1.0f / 24.0f;

#pragma unroll
    for (int r = 0; r < RPW; r++) {
        // ---- stage A: unnormalized probs, lanes = i, loop j ----
        float sse = 0.f;
        const float f1v = f1[r], f2v = f2[r];
#pragma unroll 6
        for (int j = 0; j < 24; j++) {
            float f2j = __shfl_sync(0xffffffffu, f2v, j);
            float e = f1v + f2j;
            e = (e > 0.f) ? e : 0.2f * e;              // LeakyReLU
            unsigned bits = s_adjJ[j];                 // uniform
            float p = ((bits >> lane) & 1u) ? __expf(e) : 0.f;
            sse += p;
            if (lane < 24) Pw[lane * 25 + j] = packdup(p);
        }
        // rare: fully-masked row -> reference softmax is uniform
        bool bad = (lane < 24) && (sse == 0.f);
        if (__any_sync(0xffffffffu, bad)) {
            if (bad) {
                for (int j = 0; j < 24; j++) Pw[lane * 25 + j] = packdup(1.f);
                sse = 24.f;
            }
        }
        if (lane < 24) s_rs[w * 24 + lane] = __fdividef(1.f, sse);
        __syncwarp();

        // ---- stage B: h' = attn @ Wh, lanes = k-pair, pipelined over i ----
        float acc0 = 0.f, acc1 = 0.f;
        ull pv[2][4];
        {
#pragma unroll
            for (int q = 0; q < 4; q++) pv[0][q] = Pw[q];   // i=0, g=0
        }
        ull hp0 = 0ULL, hp1 = 0ULL, hp2 = 0ULL;
        for (int i = 0; i < 24; i++) {
#pragma unroll
            for (int g = 0; g < 6; g++) {
                const int cur = g & 1, nxt = cur ^ 1;      // 6 chunks/i (even) -> parity = g&1
                // prefetch next chunk (possibly first chunk of i+1)
                if (g < 5) {
                    const ull* pr = Pw + i * 25 + (g + 1) * 4;
#pragma unroll
                    for (int q = 0; q < 4; q++) pv[nxt][q] = pr[q];
                } else if (i < 23) {
                    const ull* pr = Pw + (i + 1) * 25;
#pragma unroll
                    for (int q = 0; q < 4; q++) pv[nxt][q] = pr[q];
                }
#pragma unroll
                for (int q = 0; q < 4; q++) {
                    const int n = g * 4 + q;
                    if (g < 2)      { FMA2(hp0, pv[cur][q], wh[r][n], hp0); }
                    else if (g < 4) { FMA2(hp1, pv[cur][q], wh[r][n], hp1); }
                    else            { FMA2(hp2, pv[cur][q], wh[r][n], hp2); }
                }
                asm volatile("" ::: "memory");
            }
            ull hps, hp;
            ADD2(hps, hp0, hp1);
            ADD2(hp, hps, hp2);
            float rsv = s_rs[w * 24 + i];              // uniform
            float hx = __uint_as_float((unsigned)hp) * rsv;
            float hy = __uint_as_float((unsigned)(hp >> 32)) * rsv;
            acc0 += (hx > 0.f) ? hx : __expf(hx) - 1.f;   // ELU
            acc1 += (hy > 0.f) ? hy : __expf(hy) - 1.f;
            hp0 = hp1 = hp2 = 0ULL;
        }

        const int row = rowbase + 4 * w + r;
        float2 o; o.x = acc0 * inv24; o.y = acc1 * inv24;
        ((float2*)out)[row * 32 + lane] = o;
        __syncwarp();   // protect Pw before next sample overwrites
    }
}

// ---------------- launch ----------------
extern "C" void kernel_launch(void* const* d_in, const int* in_sizes, int n_in,
                              void* d_out, int out_size) {
    (void)in_sizes; (void)n_in; (void)out_size;
    const float* x   = (const float*)d_in[0];
    const int*   adj = (const int*)d_in[1];
    const float* Wp  = (const float*)d_in[2];
    const float* bp  = (const float*)d_in[3];
    const float* W   = (const float*)d_in[4];
    const float* a   = (const float*)d_in[5];
    float* out = (float*)d_out;

    cudaFuncSetAttribute(gat_main, cudaFuncAttributeMaxDynamicSharedMemorySize,
                         SMEM_BYTES);

    prep_wc<<<1536, 64>>>(Wp, W, a);
    prep_bc<<<24, 64>>>(bp, W, a);
    gat_main<<<GRID, NTHREADS, SMEM_BYTES>>>(x, adj, out);
}